// round 2
// baseline (speedup 1.0000x reference)
#include <cuda_runtime.h>

#define LMAX 32768
#define NMAX 32768
#define TCB 1024   // backward: candidate tile size (smem float4)
#define TTF 2048   // forward: target tile size (smem float4)

#define POSINF __int_as_float(0x7F800000)
#define NEGINF __int_as_float(0xFF800000)

// ---------------- device scratch (no allocations allowed) ----------------
__device__ unsigned int       g_keys[LMAX];
__device__ unsigned char      g_islm[LMAX];
__device__ float              g_thr;
__device__ int                g_count;
__device__ int                g_ecount;
__device__ float4             g_candC[LMAX];     // compacted kept: x,y,z, h=0.5*|c|^2
__device__ int                g_candIdx[LMAX];   // compacted kept -> original index
__device__ unsigned long long g_bwd[NMAX];       // per target: (sortable(-smax)<<32)|candOrigIdx
__device__ unsigned long long g_fwd[LMAX];       // per cand:   (sortable(-smax)<<32)|tgtIdx
__device__ float              g_num[LMAX * 3];
__device__ float              g_den[LMAX];
__device__ int                g_exact[LMAX];
__device__ float              g_exrgb[LMAX * 3];
__device__ float4             g_eC[LMAX];        // compacted empty cands: x,y,z, bits(origIdx)

// ---------------- helpers ----------------
__device__ __forceinline__ unsigned f2u(float f) {
    unsigned i = __float_as_uint(f);
    return (i & 0x80000000u) ? ~i : (i | 0x80000000u);
}
__device__ __forceinline__ float u2f(unsigned u) {
    unsigned i = (u & 0x80000000u) ? (u & 0x7FFFFFFFu) : ~u;
    return __uint_as_float(i);
}

__device__ __forceinline__ float blockReduceSum(float v) {
    __shared__ float sh[32];
    int lane = threadIdx.x & 31, w = threadIdx.x >> 5;
#pragma unroll
    for (int o = 16; o > 0; o >>= 1) v += __shfl_down_sync(0xFFFFFFFFu, v, o);
    if (lane == 0) sh[w] = v;
    __syncthreads();
    v = (threadIdx.x < (blockDim.x >> 5)) ? sh[lane] : 0.f;
    if (w == 0) {
#pragma unroll
        for (int o = 16; o > 0; o >>= 1) v += __shfl_down_sync(0xFFFFFFFFu, v, o);
    }
    return v;
}

// ---------------- kernels ----------------
__global__ void k_init(float* out, int L, int N) {
    int i = blockIdx.x * blockDim.x + threadIdx.x;
    if (i == 0) { g_count = 0; g_ecount = 0; out[0] = 0.f; out[1] = 0.f; }
    if (i < L) {
        g_num[3 * i] = 0.f; g_num[3 * i + 1] = 0.f; g_num[3 * i + 2] = 0.f;
        g_den[i] = 0.f; g_exact[i] = 0;
        g_fwd[i] = 0xFFFFFFFFFFFFFFFFULL;
    }
    if (i < N) g_bwd[i] = 0xFFFFFFFFFFFFFFFFULL;
}

// local-max over groups of 8 (first-occurrence argmax) + build sortable keys
__global__ void k_prep(const float* __restrict__ pred, int L) {
    int g = blockIdx.x * blockDim.x + threadIdx.x;
    int G = L >> 3;
    if (g >= G) return;
    const float* p = pred + g * 8;
    float bv = p[0]; int bi = 0;
#pragma unroll
    for (int j = 1; j < 8; j++) { float v = p[j]; if (v > bv) { bv = v; bi = j; } }
#pragma unroll
    for (int j = 0; j < 8; j++) {
        bool lm = (j == bi);
        g_islm[g * 8 + j] = lm ? 1 : 0;
        float f = lm ? POSINF : p[j];
        g_keys[g * 8 + j] = f2u(f);
    }
}

// single-block MSD radix select: threshold = k-th smallest of keys, k = L - points_num
__global__ void k_select(const int* __restrict__ pn, int L) {
    __shared__ unsigned hist[256];
    __shared__ unsigned s_prefix;
    __shared__ int s_rank;
    int tid = threadIdx.x;
    if (tid == 0) { s_prefix = 0u; s_rank = L - pn[0]; }
    __syncthreads();
    for (int round = 0; round < 4; round++) {
        int shift = 24 - 8 * round;
        hist[tid] = 0u;
        __syncthreads();
        unsigned pref = s_prefix;
        unsigned mask = (round == 0) ? 0u : (0xFFFFFFFFu << (shift + 8));
        for (int i = tid; i < L; i += 256) {
            unsigned u = g_keys[i];
            if ((u & mask) == pref) atomicAdd(&hist[(u >> shift) & 0xFFu], 1u);
        }
        __syncthreads();
        if (tid == 0) {
            int r = s_rank; unsigned b = 0;
            while (b < 256u) { int c = (int)hist[b]; if (c >= r) break; r -= c; b++; }
            s_rank = r;
            s_prefix = pref | (b << shift);
        }
        __syncthreads();
    }
    if (tid == 0) g_thr = u2f(s_prefix);
}

// keep mask, BCE (coord loss), warp-aggregated compaction of kept candidates
__global__ void k_keep(const float* __restrict__ pred, const int* __restrict__ kt,
                       const float* __restrict__ cxyz, int L, float* out) {
    int i = blockIdx.x * blockDim.x + threadIdx.x;
    float bce = 0.f; bool keep = false;
    float thr = g_thr;
    if (i < L) {
        float p = pred[i];
        float t = (float)kt[i];
        bce = fmaxf(p, 0.f) - p * t + log1pf(expf(-fabsf(p)));
        keep = (p > thr) || (g_islm[i] != 0);
    }
    unsigned m = __ballot_sync(0xFFFFFFFFu, keep);
    if (keep) {
        int lane = threadIdx.x & 31;
        int leader = __ffs(m) - 1;
        int base = 0;
        if (lane == leader) base = atomicAdd(&g_count, __popc(m));
        base = __shfl_sync(m, base, leader);
        int pos = base + __popc(m & ((1u << lane) - 1u));
        float x = cxyz[3 * i], y = cxyz[3 * i + 1], z = cxyz[3 * i + 2];
        float h = 0.5f * fmaf(z, z, fmaf(y, y, x * x));
        g_candC[pos] = make_float4(x, y, z, h);
        g_candIdx[pos] = i;
    }
    float s = blockReduceSum(bce);
    if (threadIdx.x == 0) atomicAdd(out, s);
}

// backward sweep: per target, argmin distance over kept candidates (tiled in smem)
__global__ void k_bwd(const float* __restrict__ txyz, int N) {
    __shared__ float4 sc[TCB];
    int count = g_count;
    int tstart = blockIdx.x * TCB;
    if (tstart >= count) return;
    for (int j = threadIdx.x; j < TCB; j += blockDim.x) {
        int p = tstart + j;
        sc[j] = (p < count) ? g_candC[p] : make_float4(0.f, 0.f, 0.f, POSINF);
    }
    __syncthreads();
    int n = blockIdx.y * blockDim.x + threadIdx.x;
    if (n >= N) return;
    float tx = txyz[3 * n], ty = txyz[3 * n + 1], tz = txyz[3 * n + 2];
    float sb0 = NEGINF, sb1 = NEGINF; int jb0 = 0, jb1 = 1;
#pragma unroll 4
    for (int j = 0; j < TCB; j += 2) {
        float4 c0 = sc[j], c1 = sc[j + 1];
        float s0 = fmaf(tx, c0.x, fmaf(ty, c0.y, fmaf(tz, c0.z, -c0.w)));
        float s1 = fmaf(tx, c1.x, fmaf(ty, c1.y, fmaf(tz, c1.z, -c1.w)));
        if (s0 > sb0) { sb0 = s0; jb0 = j; }
        if (s1 > sb1) { sb1 = s1; jb1 = j + 1; }
    }
    if (sb1 > sb0) { sb0 = sb1; jb0 = jb1; }
    int orig = g_candIdx[tstart + jb0];
    unsigned u = f2u(-sb0);  // minimize (h - dot) == minimize d^2
    atomicMin(&g_bwd[n], ((unsigned long long)u << 32) | (unsigned)orig);
}

// per target: scatter weighted rgb into the winning candidate
__global__ void k_scatter(const float* __restrict__ txyz, const float* __restrict__ trgb, int N) {
    int n = blockIdx.x * blockDim.x + threadIdx.x;
    if (n >= N) return;
    unsigned long long pk = g_bwd[n];
    if (pk == 0xFFFFFFFFFFFFFFFFULL) return;  // no kept candidates
    unsigned u = (unsigned)(pk >> 32);
    int idx = (int)(unsigned)(pk & 0xFFFFFFFFULL);
    float m = u2f(u);  // m = h - dot, d2 = t2 + 2m
    float tx = txyz[3 * n], ty = txyz[3 * n + 1], tz = txyz[3 * n + 2];
    float t2 = fmaf(tz, tz, fmaf(ty, ty, tx * tx));
    float d2 = fmaxf(fmaf(2.f, m, t2), 0.f);
    float r = trgb[3 * n], g = trgb[3 * n + 1], b = trgb[3 * n + 2];
    if (d2 == 0.f) {
        g_exact[idx] = 1;
        g_exrgb[3 * idx] = r; g_exrgb[3 * idx + 1] = g; g_exrgb[3 * idx + 2] = b;
    } else {
        float w = 1.0f / sqrtf(fmaxf(d2, 1e-30f));
        atomicAdd(&g_num[3 * idx],     r * w);
        atomicAdd(&g_num[3 * idx + 1], g * w);
        atomicAdd(&g_num[3 * idx + 2], b * w);
        atomicAdd(&g_den[idx], w);
    }
}

// compact kept candidates that received no color (the "empty" set)
__global__ void k_compactE(int L) {
    int p = blockIdx.x * blockDim.x + threadIdx.x;
    bool e = false; int l = 0;
    float4 c = make_float4(0.f, 0.f, 0.f, 0.f);
    if (p < g_count) {
        l = g_candIdx[p];
        if (g_den[l] == 0.f && g_exact[l] == 0) {
            e = true;
            c = g_candC[p];
        }
    }
    unsigned m = __ballot_sync(0xFFFFFFFFu, e);
    if (e) {
        int lane = threadIdx.x & 31;
        int leader = __ffs(m) - 1;
        int base = 0;
        if (lane == leader) base = atomicAdd(&g_ecount, __popc(m));
        base = __shfl_sync(m, base, leader);
        int pos = base + __popc(m & ((1u << lane) - 1u));
        g_eC[pos] = make_float4(c.x, c.y, c.z, __int_as_float(l));
    }
}

// forward sweep: per empty candidate, argmin distance over all targets (tiled in smem)
__global__ void k_fwd(const float* __restrict__ txyz, int N) {
    __shared__ float4 st[TTF];
    int tstart = blockIdx.y * TTF;
    for (int j = threadIdx.x; j < TTF; j += blockDim.x) {
        int t = tstart + j;
        if (t < N) {
            float x = txyz[3 * t], y = txyz[3 * t + 1], z = txyz[3 * t + 2];
            st[j] = make_float4(x, y, z, 0.5f * fmaf(z, z, fmaf(y, y, x * x)));
        } else {
            st[j] = make_float4(0.f, 0.f, 0.f, POSINF);
        }
    }
    __syncthreads();
    int e = blockIdx.x * blockDim.x + threadIdx.x;
    if (e >= g_ecount) return;
    float4 c = g_eC[e];
    float sb0 = NEGINF, sb1 = NEGINF; int jb0 = 0, jb1 = 1;
#pragma unroll 4
    for (int j = 0; j < TTF; j += 2) {
        float4 t0 = st[j], t1 = st[j + 1];
        float s0 = fmaf(c.x, t0.x, fmaf(c.y, t0.y, fmaf(c.z, t0.z, -t0.w)));
        float s1 = fmaf(c.x, t1.x, fmaf(c.y, t1.y, fmaf(c.z, t1.z, -t1.w)));
        if (s0 > sb0) { sb0 = s0; jb0 = j; }
        if (s1 > sb1) { sb1 = s1; jb1 = j + 1; }
    }
    if (sb1 > sb0) { sb0 = sb1; jb0 = jb1; }
    int l = __float_as_int(c.w);
    unsigned u = f2u(-sb0);
    atomicMin(&g_fwd[l], ((unsigned long long)u << 32) | (unsigned)(tstart + jb0));
}

// final L1 loss over kept candidates
__global__ void k_final(const float* __restrict__ crgb, const float* __restrict__ trgb,
                        float* out, int N) {
    int p = blockIdx.x * blockDim.x + threadIdx.x;
    float loss = 0.f;
    if (p < g_count) {
        int l = g_candIdx[p];
        float r0, r1, r2;
        if (g_exact[l]) {
            r0 = g_exrgb[3 * l]; r1 = g_exrgb[3 * l + 1]; r2 = g_exrgb[3 * l + 2];
        } else {
            float den = g_den[l];
            if (den != 0.f) {
                r0 = g_num[3 * l] / den;
                r1 = g_num[3 * l + 1] / den;
                r2 = g_num[3 * l + 2] / den;
            } else {
                unsigned long long pk = g_fwd[l];
                unsigned ti = (unsigned)(pk & 0xFFFFFFFFULL);
                if (ti < (unsigned)N) {
                    r0 = trgb[3 * ti]; r1 = trgb[3 * ti + 1]; r2 = trgb[3 * ti + 2];
                } else {
                    r0 = r1 = r2 = 0.f;
                }
            }
        }
        float c0 = crgb[3 * l] * 255.f;
        float c1 = crgb[3 * l + 1] * 255.f;
        float c2 = crgb[3 * l + 2] * 255.f;
        loss = fabsf(c0 - r0) + fabsf(c1 - r1) + fabsf(c2 - r2);
    }
    float s = blockReduceSum(loss);
    if (threadIdx.x == 0) atomicAdd(out + 1, s);
}

// ---------------- launch ----------------
extern "C" void kernel_launch(void* const* d_in, const int* in_sizes, int n_in,
                              void* d_out, int out_size) {
    const float* pred = (const float*)d_in[0];
    const float* cxyz = (const float*)d_in[1];
    const float* crgb = (const float*)d_in[2];
    const float* txyz = (const float*)d_in[3];
    const float* trgb = (const float*)d_in[4];
    const int*   kt   = (const int*)d_in[5];
    const int*   pn   = (const int*)d_in[6];
    float* out = (float*)d_out;

    int L = in_sizes[0];
    int N = in_sizes[3] / 3;
    int M = L > N ? L : N;

    k_init<<<(M + 255) / 256, 256>>>(out, L, N);
    k_prep<<<((L / 8) + 255) / 256, 256>>>(pred, L);
    k_select<<<1, 256>>>(pn, L);
    k_keep<<<(L + 255) / 256, 256>>>(pred, kt, cxyz, L, out);
    dim3 gb((L + TCB - 1) / TCB, (N + 255) / 256);
    k_bwd<<<gb, 256>>>(txyz, N);
    k_scatter<<<(N + 255) / 256, 256>>>(txyz, trgb, N);
    k_compactE<<<(L + 255) / 256, 256>>>(L);
    dim3 gf((L + 255) / 256, (N + TTF - 1) / TTF);
    k_fwd<<<gf, 256>>>(txyz, N);
    k_final<<<(L + 255) / 256, 256>>>(crgb, trgb, out, N);
}